// round 16
// baseline (speedup 1.0000x reference)
#include <cuda_runtime.h>
#include <cuda_fp16.h>
#include <cstdint>

#define DD       128
#define NNODES   40000
#define NEDGES   640000
#define NTHREADS 128
#define TILE_M   32
#define NGRID    592
#define NGRID_F  417          // fusedk: 3 CTAs/SM reg-limit -> 444 resident; 417 gives 3 tiles/CTA balanced

// edge smem: [0,16K) A image x2, [16K,32K) fp16 gather staging x2
#define SM_STG     16384
#define SMEM_GEMM  16384
#define SMEM_EDGE  32768
// fused smem: [0,8K) A1/H image, [8K,16K) A2 image
#define SMEM_FUSED 16384

// ---------------- global scratch ----------------
__device__ __align__(16) unsigned g_Bfrag[5][8192];
__device__ __align__(16) __half g_Ph[(size_t)NNODES * DD];    // P in fp16
__device__ __align__(16) __half g_aggh[(size_t)NNODES * DD];  // agg in fp16

// ---------------- helpers ----------------
__host__ __device__ __forceinline__ int permcol(int n) {
    int nf = (n >> 3) & 3, j = n & 7;
    return (n & ~31) | ((nf >> 1) << 4) | ((j >> 1) << 2) | ((nf & 1) << 1) | (j & 1);
}
__device__ __forceinline__ int img_offA(int c, int r, int h) {
    int i = 2 * r + h;
    i ^= (i >> 3) & 1;
    return c * 1024 + (i << 4);
}
__device__ __forceinline__ uint32_t smem_u32(const void* p) {
    uint32_t a;
    asm("{ .reg .u64 t; cvta.to.shared.u64 t, %1; cvt.u32.u64 %0, t; }" : "=r"(a) : "l"(p));
    return a;
}
__device__ __forceinline__ uint32_t ldm_addrA(uint32_t base, int c, int mf, int lane) {
    int r = mf * 16 + ((lane >> 3) & 1) * 8 + (lane & 7);
    int h = lane >> 4;
    int i = 2 * r + h;
    i ^= (i >> 3) & 1;
    return base + c * 1024 + (i << 4);
}

#define LDM4(d, addr) \
    asm volatile("ldmatrix.sync.aligned.m8n8.x4.shared.b16 {%0,%1,%2,%3}, [%4];" \
                 : "=r"((d)[0]), "=r"((d)[1]), "=r"((d)[2]), "=r"((d)[3]) : "r"(addr))

#define MMA(d, a, b0, b1) \
    asm volatile("mma.sync.aligned.m16n8k16.row.col.f32.f16.f16.f32 " \
                 "{%0,%1,%2,%3}, {%4,%5,%6,%7}, {%8,%9}, {%0,%1,%2,%3};" \
                 : "+f"((d)[0]), "+f"((d)[1]), "+f"((d)[2]), "+f"((d)[3]) \
                 : "r"((a)[0]), "r"((a)[1]), "r"((a)[2]), "r"((a)[3]), "r"(b0), "r"(b1))

#define CP_ASYNC16(dst, src) \
    asm volatile("cp.async.cg.shared.global [%0], [%1], 16;" :: "r"(dst), "l"(src))
#define CP_COMMIT() asm volatile("cp.async.commit_group;" ::: "memory")
#define CP_WAIT0()  asm volatile("cp.async.wait_group 0;" ::: "memory")

// silu via tanh.approx: 1 MUFU + 2 FMA
__device__ __forceinline__ float silu_f(float x) {
    float t;
    asm("tanh.approx.f32 %0, %1;" : "=f"(t) : "f"(0.5f * x));
    return x * fmaf(0.5f, t, 0.5f);
}

__device__ __forceinline__ uint32_t pk_h2(__half a, __half b) {
    __half2 t = __halves2half2(a, b);
    return *(uint32_t*)&t;
}
// packed fp32x2 -> fp16x2 conversion (single F2FP)
__device__ __forceinline__ uint32_t pk2f(float a, float b) {
    __half2 t = __float22half2_rn(make_float2(a, b));
    return *(uint32_t*)&t;
}

// fp16 vector reduction: adds 4 halves (2 x f16x2) at p
__device__ __forceinline__ void red_add_h4(__half* p, float v0, float v1,
                                           float v2, float v3) {
    uint32_t h0 = pk2f(v0, v1);
    uint32_t h1 = pk2f(v2, v3);
    asm volatile("red.global.add.noftz.v2.f16x2 [%0], {%1, %2};"
                 :: "l"(p), "r"(h0), "r"(h1) : "memory");
}

// load one B chunk (8 u32 frags) from gmem fragment image (L2-hit)
__device__ __forceinline__ void ldB(uint32_t* b8, const unsigned* __restrict__ Bsrc,
                                    int wn, int c, int lane) {
    const uint4* bp = (const uint4*)Bsrc + ((wn * 8 + c) * 32 + lane) * 2;
    uint4 u0 = __ldg(bp);
    uint4 u1 = __ldg(bp + 1);
    b8[0] = u0.x; b8[1] = u0.y; b8[2] = u0.z; b8[3] = u0.w;
    b8[4] = u1.x; b8[5] = u1.y; b8[6] = u1.z; b8[7] = u1.w;
}

// ---------------- prep: B fragment images + zero agg ----------------
__global__ void prep_kernel(const float* __restrict__ mw1, const float* __restrict__ uw1,
                            const float* __restrict__ uw2) {
    if (blockIdx.x < 5) {
        const int which = blockIdx.x;
        const float* W;
        switch (which) {
            case 0: W = mw1; break;
            case 1: W = mw1 + DD * DD; break;
            case 2: W = uw1; break;
            case 3: W = uw1 + DD * DD; break;
            default: W = uw2; break;
        }
        unsigned* dst = &g_Bfrag[which][0];
        for (int e = threadIdx.x; e < 8192; e += blockDim.x) {
            int wn = e >> 11, c = (e >> 8) & 7, lane = (e >> 3) & 31, j = e & 7;
            int nf = j >> 1, h = j & 1;
            int n = wn * 32 + nf * 8 + (lane >> 2);
            int col = permcol(n);
            int k = c * 16 + h * 8 + (lane & 3) * 2;
            dst[e] = pk2f(W[k * DD + col], W[(k + 1) * DD + col]);
        }
    } else {
        const int b = blockIdx.x - 5;
        uint4* p = (uint4*)g_aggh;
        const int n16 = NNODES * DD / 8;
        for (int i = b * (int)blockDim.x + threadIdx.x; i < n16; i += 64 * (int)blockDim.x)
            p[i] = make_uint4(0u, 0u, 0u, 0u);
    }
}

// ---------------- A tile converts ----------------
__device__ __forceinline__ void convertA(char* buf, const float* __restrict__ A,
                                         long rowbase) {
    const int r = threadIdx.x & 31;
    const int cseg = (threadIdx.x >> 5) << 5;
    const float4* srcp = (const float4*)(A + (rowbase + r) * DD + cseg);
#pragma unroll
    for (int j = 0; j < 4; j++) {
        float4 u = __ldg(srcp + 2 * j);
        float4 v = __ldg(srcp + 2 * j + 1);
        const int col0 = cseg + j * 8;
        const int c = col0 >> 4, h = (col0 >> 3) & 1;
        *(uint4*)(buf + img_offA(c, r, h)) = make_uint4(
            pk2f(u.x, u.y), pk2f(u.z, u.w), pk2f(v.x, v.y), pk2f(v.z, v.w));
    }
}
__device__ __forceinline__ void convertAh(char* buf, const __half* __restrict__ A,
                                          long rowbase) {
    const int r = threadIdx.x & 31;
    const int cseg = (threadIdx.x >> 5) << 5;
    const uint4* srcp = (const uint4*)(A + (rowbase + r) * DD + cseg);
#pragma unroll
    for (int j = 0; j < 4; j++) {
        uint4 u = __ldg(srcp + j);
        const int col0 = cseg + j * 8;
        const int c = col0 >> 4, h = (col0 >> 3) & 1;
        *(uint4*)(buf + img_offA(c, r, h)) = u;
    }
}

// ---------------- main GEMM kernel (P stage + edge stage) ----------------
// R11 structure: B register cache, A double-buffered LDG-convert, gather staged
// via cp.async one tile ahead, fp16 scatter.
template <bool BIAS, bool ADD, bool GATHER, bool SILU, bool SCATTER, bool OUTH>
__global__ void __launch_bounds__(NTHREADS, 4)
tgemm(const float* __restrict__ A, const unsigned* __restrict__ Bf,
      const void* __restrict__ addv, const float* __restrict__ bias,
      const int* __restrict__ gsrc, const int* __restrict__ gdst,
      void* __restrict__ Out, int nrows) {
    extern __shared__ char sm[];
    __shared__ int s_dst[2][TILE_M];
    const uint32_t As = smem_u32(sm);
    const int tid = threadIdx.x, lane = tid & 31, wn = tid >> 5;
    const int srow = tid >> 2;
    const int qseg = (tid & 3) << 2;

    uint32_t bf[8][8];
#pragma unroll
    for (int c = 0; c < 8; c++) ldB(bf[c], Bf, wn, c, lane);

    float4 bias_r[2];
#pragma unroll
    for (int p = 0; p < 2; p++)
        bias_r[p] = BIAS
            ? __ldg((const float4*)(bias + wn * 32 + p * 16 + (lane & 3) * 4))
            : make_float4(0.f, 0.f, 0.f, 0.f);

    const int tiles = nrows / TILE_M;
    const int bid = blockIdx.x;
    if (bid >= tiles) return;
    const int ntb = (tiles - 1 - bid) / (int)gridDim.x + 1;

    convertA(sm, A, (long)bid * TILE_M);
    int idx_next = 0;
    if (GATHER) {
        int idx0 = __ldg(gsrc + (long)bid * TILE_M + srow);
        const __half* gp = (const __half*)addv + (size_t)idx0 * DD;
        uint32_t sd = As + SM_STG + srow * 256;
#pragma unroll
        for (int i = 0; i < 4; i++) {
            int ch = qseg + i;
            CP_ASYNC16(sd + ((ch ^ (srow & 7)) << 4), gp + ch * 8);
        }
        CP_COMMIT();
        if (ntb > 1)
            idx_next = __ldg(gsrc + ((long)bid + gridDim.x) * TILE_M + srow);
    }
    if (SCATTER && tid >= TILE_M && tid < 2 * TILE_M)
        s_dst[0][tid - TILE_M] = __ldg(gdst + (long)bid * TILE_M + (tid - TILE_M));

    for (int it = 0; it < ntb; it++) {
        const long tile = (long)bid + (long)it * gridDim.x;
        const long rowbase = tile * TILE_M;
        const int pb = it & 1;
        if (GATHER) CP_WAIT0();
        __syncthreads();

        float acc[2][4][4];
#pragma unroll
        for (int mf = 0; mf < 2; mf++)
#pragma unroll
            for (int nf = 0; nf < 4; nf++)
#pragma unroll
                for (int q = 0; q < 4; q++) acc[mf][nf][q] = 0.f;

        const uint32_t Ab = As + pb * 8192;
#pragma unroll
        for (int c = 0; c < 8; c++) {
            uint32_t a[2][4];
            LDM4(a[0], ldm_addrA(Ab, c, 0, lane));
            LDM4(a[1], ldm_addrA(Ab, c, 1, lane));
#pragma unroll
            for (int mf = 0; mf < 2; mf++)
#pragma unroll
                for (int nf = 0; nf < 4; nf++)
                    MMA(acc[mf][nf], a[mf], bf[c][2 * nf], bf[c][2 * nf + 1]);
        }

        if (it + 1 < ntb) {
            const long nt = tile + gridDim.x;
            convertA(sm + (pb ^ 1) * 8192, A, nt * TILE_M);
            if (GATHER) {
                const __half* gp = (const __half*)addv + (size_t)idx_next * DD;
                uint32_t sd = As + SM_STG + (pb ^ 1) * 8192 + srow * 256;
#pragma unroll
                for (int i = 0; i < 4; i++) {
                    int ch = qseg + i;
                    CP_ASYNC16(sd + ((ch ^ (srow & 7)) << 4), gp + ch * 8);
                }
                CP_COMMIT();
                if (it + 2 < ntb)
                    idx_next = __ldg(gsrc + (nt + gridDim.x) * TILE_M + srow);
            }
            if (SCATTER && tid >= TILE_M && tid < 2 * TILE_M)
                s_dst[pb ^ 1][tid - TILE_M] = __ldg(gdst + nt * TILE_M + (tid - TILE_M));
        }

        {
            const int q = lane & 3, ro = lane >> 2;
            const char* stg = sm + SM_STG + pb * 8192;
#pragma unroll
            for (int mf = 0; mf < 2; mf++) {
#pragma unroll
                for (int rh = 0; rh < 2; rh++) {
                    const int r = mf * 16 + rh * 8 + ro;
                    const long gr = rowbase + r;
                    const long orow = SCATTER ? (long)s_dst[pb][r] : gr;
#pragma unroll
                    for (int p = 0; p < 2; p++) {
                        const int cc = wn * 32 + p * 16 + q * 4;
                        float v0 = acc[mf][2 * p][2 * rh];
                        float v1 = acc[mf][2 * p][2 * rh + 1];
                        float v2 = acc[mf][2 * p + 1][2 * rh];
                        float v3 = acc[mf][2 * p + 1][2 * rh + 1];
                        if (ADD) {
                            if (GATHER) {
                                const int ch = wn * 4 + p * 2 + (q >> 1);
                                uint2 hv = *(const uint2*)(stg + r * 256 +
                                            ((ch ^ (r & 7)) << 4) + (q & 1) * 8);
                                float2 f0 = __half22float2(*(__half2*)&hv.x);
                                float2 f1 = __half22float2(*(__half2*)&hv.y);
                                v0 += f0.x; v1 += f0.y; v2 += f1.x; v3 += f1.y;
                            } else {
                                float4 t = __ldg((const float4*)((const float*)addv +
                                                                 gr * DD + cc));
                                v0 += t.x; v1 += t.y; v2 += t.z; v3 += t.w;
                            }
                        }
                        if (BIAS) {
                            float4 b = bias_r[p];
                            v0 += b.x; v1 += b.y; v2 += b.z; v3 += b.w;
                        }
                        if (SILU) {
                            v0 = silu_f(v0); v1 = silu_f(v1);
                            v2 = silu_f(v2); v3 = silu_f(v3);
                        }
                        if (OUTH) {
                            __half* oh = (__half*)Out + orow * DD + cc;
                            *(uint2*)oh = make_uint2(pk2f(v0, v1), pk2f(v2, v3));
                        } else if (SCATTER) {
                            red_add_h4((__half*)Out + orow * DD + cc, v0, v1, v2, v3);
                        } else {
                            *(float4*)((float*)Out + orow * DD + cc) =
                                make_float4(v0, v1, v2, v3);
                        }
                    }
                }
            }
        }
    }
}

// ---------------- fused node-update kernel (stages 3+4+5) ----------------
__global__ void __launch_bounds__(NTHREADS, 3)
fusedk(const float* __restrict__ nodes, const __half* __restrict__ aggh,
       const unsigned* __restrict__ Bt, const unsigned* __restrict__ Bb,
       const unsigned* __restrict__ B2, const float* __restrict__ ub1,
       const float* __restrict__ ub2, float* __restrict__ Out) {
    extern __shared__ char sm[];
    const uint32_t As = smem_u32(sm);
    const int tid = threadIdx.x, lane = tid & 31, wn = tid >> 5;
    const int q = lane & 3, ro = lane >> 2;

    float4 b1r[2], b2r[2];
#pragma unroll
    for (int p = 0; p < 2; p++) {
        b1r[p] = __ldg((const float4*)(ub1 + wn * 32 + p * 16 + q * 4));
        b2r[p] = __ldg((const float4*)(ub2 + wn * 32 + p * 16 + q * 4));
    }

    const int tiles = NNODES / TILE_M;
    for (int tile = blockIdx.x; tile < tiles; tile += (int)gridDim.x) {
        const long rowbase = (long)tile * TILE_M;
        convertA(sm, nodes, rowbase);
        convertAh(sm + 8192, aggh, rowbase);
        __syncthreads();

        float acc[2][4][4];
#pragma unroll
        for (int mf = 0; mf < 2; mf++)
#pragma unroll
            for (int nf = 0; nf < 4; nf++)
#pragma unroll
                for (int qq = 0; qq < 4; qq++) acc[mf][nf][qq] = 0.f;

#pragma unroll
        for (int c = 0; c < 8; c++) {
            uint32_t a[2][4], bfr[8];
            ldB(bfr, Bt, wn, c, lane);
            LDM4(a[0], ldm_addrA(As, c, 0, lane));
            LDM4(a[1], ldm_addrA(As, c, 1, lane));
#pragma unroll
            for (int mf = 0; mf < 2; mf++)
#pragma unroll
                for (int nf = 0; nf < 4; nf++)
                    MMA(acc[mf][nf], a[mf], bfr[2 * nf], bfr[2 * nf + 1]);
        }
#pragma unroll
        for (int c = 0; c < 8; c++) {
            uint32_t a[2][4], bfr[8];
            ldB(bfr, Bb, wn, c, lane);
            LDM4(a[0], ldm_addrA(As + 8192, c, 0, lane));
            LDM4(a[1], ldm_addrA(As + 8192, c, 1, lane));
#pragma unroll
            for (int mf = 0; mf < 2; mf++)
#pragma unroll
                for (int nf = 0; nf < 4; nf++)
                    MMA(acc[mf][nf], a[mf], bfr[2 * nf], bfr[2 * nf + 1]);
        }
        __syncthreads();

#pragma unroll
        for (int mf = 0; mf < 2; mf++) {
#pragma unroll
            for (int rh = 0; rh < 2; rh++) {
                const int r = mf * 16 + rh * 8 + ro;
#pragma unroll
                for (int p = 0; p < 2; p++) {
                    float4 b = b1r[p];
                    float v0 = silu_f(acc[mf][2 * p][2 * rh] + b.x);
                    float v1 = silu_f(acc[mf][2 * p][2 * rh + 1] + b.y);
                    float v2 = silu_f(acc[mf][2 * p + 1][2 * rh] + b.z);
                    float v3 = silu_f(acc[mf][2 * p + 1][2 * rh + 1] + b.w);
                    uint2 hv = make_uint2(pk2f(v0, v1), pk2f(v2, v3));
                    *(uint2*)(sm + img_offA(wn * 2 + p, r, q >> 1) + (q & 1) * 8) = hv;
                }
            }
        }
        __syncthreads();

#pragma unroll
        for (int mf = 0; mf < 2; mf++)
#pragma unroll
            for (int nf = 0; nf < 4; nf++)
#pragma unroll
                for (int qq = 0; qq < 4; qq++) acc[mf][nf][qq] = 0.f;
#pragma unroll
        for (int c = 0; c < 8; c++) {
            uint32_t a[2][4], bfr[8];
            ldB(bfr, B2, wn, c, lane);
            LDM4(a[0], ldm_addrA(As, c, 0, lane));
            LDM4(a[1], ldm_addrA(As, c, 1, lane));
#pragma unroll
            for (int mf = 0; mf < 2; mf++)
#pragma unroll
                for (int nf = 0; nf < 4; nf++)
                    MMA(acc[mf][nf], a[mf], bfr[2 * nf], bfr[2 * nf + 1]);
        }
#pragma unroll
        for (int mf = 0; mf < 2; mf++) {
#pragma unroll
            for (int rh = 0; rh < 2; rh++) {
                const int r = mf * 16 + rh * 8 + ro;
                const long gr = rowbase + r;
#pragma unroll
                for (int p = 0; p < 2; p++) {
                    const int cc = wn * 32 + p * 16 + q * 4;
                    float4 t = __ldg((const float4*)(nodes + gr * DD + cc));
                    float4 b = b2r[p];
                    *(float4*)(Out + gr * DD + cc) = make_float4(
                        acc[mf][2 * p][2 * rh] + t.x + b.x,
                        acc[mf][2 * p][2 * rh + 1] + t.y + b.y,
                        acc[mf][2 * p + 1][2 * rh] + t.z + b.z,
                        acc[mf][2 * p + 1][2 * rh + 1] + t.w + b.w);
                }
            }
        }
        __syncthreads();
    }
}

// ---------------- launch ----------------
extern "C" void kernel_launch(void* const* d_in, const int* in_sizes, int n_in,
                              void* d_out, int out_size) {
    const float* nodes = (const float*)d_in[0];
    const int*   ei    = (const int*)d_in[1];
    const float* ef    = (const float*)d_in[2];
    const float* mw1   = (const float*)d_in[3];
    const float* mb1   = (const float*)d_in[4];
    const float* uw1   = (const float*)d_in[5];
    const float* ub1   = (const float*)d_in[6];
    const float* uw2   = (const float*)d_in[7];
    const float* ub2   = (const float*)d_in[8];
    float* out = (float*)d_out;

    unsigned* Bf;
    __half *Ph, *aggh;
    cudaGetSymbolAddress((void**)&Bf,   g_Bfrag);
    cudaGetSymbolAddress((void**)&Ph,   g_Ph);
    cudaGetSymbolAddress((void**)&aggh, g_aggh);

    cudaFuncSetAttribute(tgemm<false, true, true, true, true, false>,
                         cudaFuncAttributeMaxDynamicSharedMemorySize, SMEM_EDGE);

    // 0) B fragment images + zero agg
    prep_kernel<<<69, 256>>>(mw1, uw1, uw2);
    // 1) Ph = fp16(nodes @ mw1_top + mb1)
    tgemm<true, false, false, false, false, true><<<NGRID, NTHREADS, SMEM_GEMM>>>(
        nodes, Bf + 0 * 8192, nullptr, mb1, nullptr, nullptr, Ph, NNODES);
    // 2) aggh[dst] += fp16(silu(ef @ mw1_bot + Ph[src]))
    tgemm<false, true, true, true, true, false><<<NGRID, NTHREADS, SMEM_EDGE>>>(
        ef, Bf + 1 * 8192, Ph, nullptr, ei, ei + NEDGES, aggh, NEDGES);
    // 3) out = silu([nodes|aggh] @ uw1 + ub1) @ uw2 + nodes + ub2  (fused)
    fusedk<<<NGRID_F, NTHREADS, SMEM_FUSED>>>(
        nodes, aggh, Bf + 2 * 8192, Bf + 3 * 8192, Bf + 4 * 8192, ub1, ub2, out);
}

// round 17
// speedup vs baseline: 1.0061x; 1.0061x over previous
#include <cuda_runtime.h>
#include <cuda_fp16.h>
#include <cstdint>

#define DD       128
#define NNODES   40000
#define NEDGES   640000
#define NTHREADS 128
#define TILE_M   32
#define NGRID    592
#define NGRID_F  417          // fusedk: 3 CTAs/SM reg-limit -> 444 resident; 417 gives 3 tiles/CTA balanced

// edge smem: [0,16K) A image x2, [16K,32K) fp16 gather staging x2
#define SM_STG     16384
#define SMEM_GEMM  16384
#define SMEM_EDGE  32768
// fused smem: [0,8K) A1/H image, [8K,16K) A2 image
#define SMEM_FUSED 16384

// ---------------- global scratch ----------------
__device__ __align__(16) unsigned g_Bfrag[5][8192];
__device__ __align__(16) __half g_Ph[(size_t)NNODES * DD];    // P in fp16
__device__ __align__(16) __half g_aggh[(size_t)NNODES * DD];  // agg in fp16

// ---------------- helpers ----------------
__host__ __device__ __forceinline__ int permcol(int n) {
    int nf = (n >> 3) & 3, j = n & 7;
    return (n & ~31) | ((nf >> 1) << 4) | ((j >> 1) << 2) | ((nf & 1) << 1) | (j & 1);
}
__device__ __forceinline__ int img_offA(int c, int r, int h) {
    int i = 2 * r + h;
    i ^= (i >> 3) & 1;
    return c * 1024 + (i << 4);
}
__device__ __forceinline__ uint32_t smem_u32(const void* p) {
    uint32_t a;
    asm("{ .reg .u64 t; cvta.to.shared.u64 t, %1; cvt.u32.u64 %0, t; }" : "=r"(a) : "l"(p));
    return a;
}
__device__ __forceinline__ uint32_t ldm_addrA(uint32_t base, int c, int mf, int lane) {
    int r = mf * 16 + ((lane >> 3) & 1) * 8 + (lane & 7);
    int h = lane >> 4;
    int i = 2 * r + h;
    i ^= (i >> 3) & 1;
    return base + c * 1024 + (i << 4);
}

#define LDM4(d, addr) \
    asm volatile("ldmatrix.sync.aligned.m8n8.x4.shared.b16 {%0,%1,%2,%3}, [%4];" \
                 : "=r"((d)[0]), "=r"((d)[1]), "=r"((d)[2]), "=r"((d)[3]) : "r"(addr))

#define MMA(d, a, b0, b1) \
    asm volatile("mma.sync.aligned.m16n8k16.row.col.f32.f16.f16.f32 " \
                 "{%0,%1,%2,%3}, {%4,%5,%6,%7}, {%8,%9}, {%0,%1,%2,%3};" \
                 : "+f"((d)[0]), "+f"((d)[1]), "+f"((d)[2]), "+f"((d)[3]) \
                 : "r"((a)[0]), "r"((a)[1]), "r"((a)[2]), "r"((a)[3]), "r"(b0), "r"(b1))

#define CP_ASYNC16(dst, src) \
    asm volatile("cp.async.cg.shared.global [%0], [%1], 16;" :: "r"(dst), "l"(src))
#define CP_COMMIT() asm volatile("cp.async.commit_group;" ::: "memory")
#define CP_WAIT0()  asm volatile("cp.async.wait_group 0;" ::: "memory")

// silu via tanh.approx: 1 MUFU + 2 FMA
__device__ __forceinline__ float silu_f(float x) {
    float t;
    asm("tanh.approx.f32 %0, %1;" : "=f"(t) : "f"(0.5f * x));
    return x * fmaf(0.5f, t, 0.5f);
}

__device__ __forceinline__ uint32_t pk_h2(__half a, __half b) {
    __half2 t = __halves2half2(a, b);
    return *(uint32_t*)&t;
}
// packed fp32x2 -> fp16x2 conversion (single F2FP)
__device__ __forceinline__ uint32_t pk2f(float a, float b) {
    __half2 t = __float22half2_rn(make_float2(a, b));
    return *(uint32_t*)&t;
}

// fp16 vector reduction: adds 4 halves (2 x f16x2) at p
__device__ __forceinline__ void red_add_h4(__half* p, float v0, float v1,
                                           float v2, float v3) {
    uint32_t h0 = pk2f(v0, v1);
    uint32_t h1 = pk2f(v2, v3);
    asm volatile("red.global.add.noftz.v2.f16x2 [%0], {%1, %2};"
                 :: "l"(p), "r"(h0), "r"(h1) : "memory");
}

// load one B chunk (8 u32 frags) from gmem fragment image (L2-hit)
__device__ __forceinline__ void ldB(uint32_t* b8, const unsigned* __restrict__ Bsrc,
                                    int wn, int c, int lane) {
    const uint4* bp = (const uint4*)Bsrc + ((wn * 8 + c) * 32 + lane) * 2;
    uint4 u0 = __ldg(bp);
    uint4 u1 = __ldg(bp + 1);
    b8[0] = u0.x; b8[1] = u0.y; b8[2] = u0.z; b8[3] = u0.w;
    b8[4] = u1.x; b8[5] = u1.y; b8[6] = u1.z; b8[7] = u1.w;
}

// ---------------- prep: B fragment images + zero agg ----------------
__global__ void prep_kernel(const float* __restrict__ mw1, const float* __restrict__ uw1,
                            const float* __restrict__ uw2) {
    if (blockIdx.x < 5) {
        const int which = blockIdx.x;
        const float* W;
        switch (which) {
            case 0: W = mw1; break;
            case 1: W = mw1 + DD * DD; break;
            case 2: W = uw1; break;
            case 3: W = uw1 + DD * DD; break;
            default: W = uw2; break;
        }
        unsigned* dst = &g_Bfrag[which][0];
        for (int e = threadIdx.x; e < 8192; e += blockDim.x) {
            int wn = e >> 11, c = (e >> 8) & 7, lane = (e >> 3) & 31, j = e & 7;
            int nf = j >> 1, h = j & 1;
            int n = wn * 32 + nf * 8 + (lane >> 2);
            int col = permcol(n);
            int k = c * 16 + h * 8 + (lane & 3) * 2;
            dst[e] = pk2f(W[k * DD + col], W[(k + 1) * DD + col]);
        }
    } else {
        const int b = blockIdx.x - 5;
        uint4* p = (uint4*)g_aggh;
        const int n16 = NNODES * DD / 8;
        for (int i = b * (int)blockDim.x + threadIdx.x; i < n16; i += 64 * (int)blockDim.x)
            p[i] = make_uint4(0u, 0u, 0u, 0u);
    }
}

// ---------------- A tile converts ----------------
// STREAM variant: evict-first loads for one-touch data (EF stream)
template <bool STREAM>
__device__ __forceinline__ void convertA(char* buf, const float* __restrict__ A,
                                         long rowbase) {
    const int r = threadIdx.x & 31;
    const int cseg = (threadIdx.x >> 5) << 5;
    const float4* srcp = (const float4*)(A + (rowbase + r) * DD + cseg);
#pragma unroll
    for (int j = 0; j < 4; j++) {
        float4 u = STREAM ? __ldcs(srcp + 2 * j)     : __ldg(srcp + 2 * j);
        float4 v = STREAM ? __ldcs(srcp + 2 * j + 1) : __ldg(srcp + 2 * j + 1);
        const int col0 = cseg + j * 8;
        const int c = col0 >> 4, h = (col0 >> 3) & 1;
        *(uint4*)(buf + img_offA(c, r, h)) = make_uint4(
            pk2f(u.x, u.y), pk2f(u.z, u.w), pk2f(v.x, v.y), pk2f(v.z, v.w));
    }
}
__device__ __forceinline__ void convertAh(char* buf, const __half* __restrict__ A,
                                          long rowbase) {
    const int r = threadIdx.x & 31;
    const int cseg = (threadIdx.x >> 5) << 5;
    const uint4* srcp = (const uint4*)(A + (rowbase + r) * DD + cseg);
#pragma unroll
    for (int j = 0; j < 4; j++) {
        uint4 u = __ldcs(srcp + j);   // aggh read once per kernel
        const int col0 = cseg + j * 8;
        const int c = col0 >> 4, h = (col0 >> 3) & 1;
        *(uint4*)(buf + img_offA(c, r, h)) = u;
    }
}

// ---------------- main GEMM kernel (P stage + edge stage) ----------------
// R11 structure: B register cache, A double-buffered LDG-convert, gather staged
// via cp.async one tile ahead, fp16 scatter. A-stream loads use evict-first.
template <bool BIAS, bool ADD, bool GATHER, bool SILU, bool SCATTER, bool OUTH>
__global__ void __launch_bounds__(NTHREADS, 4)
tgemm(const float* __restrict__ A, const unsigned* __restrict__ Bf,
      const void* __restrict__ addv, const float* __restrict__ bias,
      const int* __restrict__ gsrc, const int* __restrict__ gdst,
      void* __restrict__ Out, int nrows) {
    extern __shared__ char sm[];
    __shared__ int s_dst[2][TILE_M];
    const uint32_t As = smem_u32(sm);
    const int tid = threadIdx.x, lane = tid & 31, wn = tid >> 5;
    const int srow = tid >> 2;
    const int qseg = (tid & 3) << 2;

    uint32_t bf[8][8];
#pragma unroll
    for (int c = 0; c < 8; c++) ldB(bf[c], Bf, wn, c, lane);

    float4 bias_r[2];
#pragma unroll
    for (int p = 0; p < 2; p++)
        bias_r[p] = BIAS
            ? __ldg((const float4*)(bias + wn * 32 + p * 16 + (lane & 3) * 4))
            : make_float4(0.f, 0.f, 0.f, 0.f);

    const int tiles = nrows / TILE_M;
    const int bid = blockIdx.x;
    if (bid >= tiles) return;
    const int ntb = (tiles - 1 - bid) / (int)gridDim.x + 1;

    convertA<true>(sm, A, (long)bid * TILE_M);
    int idx_next = 0;
    if (GATHER) {
        int idx0 = __ldg(gsrc + (long)bid * TILE_M + srow);
        const __half* gp = (const __half*)addv + (size_t)idx0 * DD;
        uint32_t sd = As + SM_STG + srow * 256;
#pragma unroll
        for (int i = 0; i < 4; i++) {
            int ch = qseg + i;
            CP_ASYNC16(sd + ((ch ^ (srow & 7)) << 4), gp + ch * 8);
        }
        CP_COMMIT();
        if (ntb > 1)
            idx_next = __ldg(gsrc + ((long)bid + gridDim.x) * TILE_M + srow);
    }
    if (SCATTER && tid >= TILE_M && tid < 2 * TILE_M)
        s_dst[0][tid - TILE_M] = __ldg(gdst + (long)bid * TILE_M + (tid - TILE_M));

    for (int it = 0; it < ntb; it++) {
        const long tile = (long)bid + (long)it * gridDim.x;
        const long rowbase = tile * TILE_M;
        const int pb = it & 1;
        if (GATHER) CP_WAIT0();
        __syncthreads();

        float acc[2][4][4];
#pragma unroll
        for (int mf = 0; mf < 2; mf++)
#pragma unroll
            for (int nf = 0; nf < 4; nf++)
#pragma unroll
                for (int q = 0; q < 4; q++) acc[mf][nf][q] = 0.f;

        const uint32_t Ab = As + pb * 8192;
#pragma unroll
        for (int c = 0; c < 8; c++) {
            uint32_t a[2][4];
            LDM4(a[0], ldm_addrA(Ab, c, 0, lane));
            LDM4(a[1], ldm_addrA(Ab, c, 1, lane));
#pragma unroll
            for (int mf = 0; mf < 2; mf++)
#pragma unroll
                for (int nf = 0; nf < 4; nf++)
                    MMA(acc[mf][nf], a[mf], bf[c][2 * nf], bf[c][2 * nf + 1]);
        }

        if (it + 1 < ntb) {
            const long nt = tile + gridDim.x;
            convertA<true>(sm + (pb ^ 1) * 8192, A, nt * TILE_M);
            if (GATHER) {
                const __half* gp = (const __half*)addv + (size_t)idx_next * DD;
                uint32_t sd = As + SM_STG + (pb ^ 1) * 8192 + srow * 256;
#pragma unroll
                for (int i = 0; i < 4; i++) {
                    int ch = qseg + i;
                    CP_ASYNC16(sd + ((ch ^ (srow & 7)) << 4), gp + ch * 8);
                }
                CP_COMMIT();
                if (it + 2 < ntb)
                    idx_next = __ldg(gsrc + (nt + gridDim.x) * TILE_M + srow);
            }
            if (SCATTER && tid >= TILE_M && tid < 2 * TILE_M)
                s_dst[pb ^ 1][tid - TILE_M] = __ldg(gdst + nt * TILE_M + (tid - TILE_M));
        }

        {
            const int q = lane & 3, ro = lane >> 2;
            const char* stg = sm + SM_STG + pb * 8192;
#pragma unroll
            for (int mf = 0; mf < 2; mf++) {
#pragma unroll
                for (int rh = 0; rh < 2; rh++) {
                    const int r = mf * 16 + rh * 8 + ro;
                    const long gr = rowbase + r;
                    const long orow = SCATTER ? (long)s_dst[pb][r] : gr;
#pragma unroll
                    for (int p = 0; p < 2; p++) {
                        const int cc = wn * 32 + p * 16 + q * 4;
                        float v0 = acc[mf][2 * p][2 * rh];
                        float v1 = acc[mf][2 * p][2 * rh + 1];
                        float v2 = acc[mf][2 * p + 1][2 * rh];
                        float v3 = acc[mf][2 * p + 1][2 * rh + 1];
                        if (ADD) {
                            if (GATHER) {
                                const int ch = wn * 4 + p * 2 + (q >> 1);
                                uint2 hv = *(const uint2*)(stg + r * 256 +
                                            ((ch ^ (r & 7)) << 4) + (q & 1) * 8);
                                float2 f0 = __half22float2(*(__half2*)&hv.x);
                                float2 f1 = __half22float2(*(__half2*)&hv.y);
                                v0 += f0.x; v1 += f0.y; v2 += f1.x; v3 += f1.y;
                            } else {
                                float4 t = __ldg((const float4*)((const float*)addv +
                                                                 gr * DD + cc));
                                v0 += t.x; v1 += t.y; v2 += t.z; v3 += t.w;
                            }
                        }
                        if (BIAS) {
                            float4 b = bias_r[p];
                            v0 += b.x; v1 += b.y; v2 += b.z; v3 += b.w;
                        }
                        if (SILU) {
                            v0 = silu_f(v0); v1 = silu_f(v1);
                            v2 = silu_f(v2); v3 = silu_f(v3);
                        }
                        if (OUTH) {
                            __half* oh = (__half*)Out + orow * DD + cc;
                            *(uint2*)oh = make_uint2(pk2f(v0, v1), pk2f(v2, v3));
                        } else if (SCATTER) {
                            red_add_h4((__half*)Out + orow * DD + cc, v0, v1, v2, v3);
                        } else {
                            *(float4*)((float*)Out + orow * DD + cc) =
                                make_float4(v0, v1, v2, v3);
                        }
                    }
                }
            }
        }
    }
}

// ---------------- fused node-update kernel (stages 3+4+5) ----------------
__global__ void __launch_bounds__(NTHREADS, 3)
fusedk(const float* __restrict__ nodes, const __half* __restrict__ aggh,
       const unsigned* __restrict__ Bt, const unsigned* __restrict__ Bb,
       const unsigned* __restrict__ B2, const float* __restrict__ ub1,
       const float* __restrict__ ub2, float* __restrict__ Out) {
    extern __shared__ char sm[];
    const uint32_t As = smem_u32(sm);
    const int tid = threadIdx.x, lane = tid & 31, wn = tid >> 5;
    const int q = lane & 3, ro = lane >> 2;

    float4 b1r[2], b2r[2];
#pragma unroll
    for (int p = 0; p < 2; p++) {
        b1r[p] = __ldg((const float4*)(ub1 + wn * 32 + p * 16 + q * 4));
        b2r[p] = __ldg((const float4*)(ub2 + wn * 32 + p * 16 + q * 4));
    }

    const int tiles = NNODES / TILE_M;
    for (int tile = blockIdx.x; tile < tiles; tile += (int)gridDim.x) {
        const long rowbase = (long)tile * TILE_M;
        convertA<false>(sm, nodes, rowbase);   // nodes re-read in epilogue -> keep cached
        convertAh(sm + 8192, aggh, rowbase);
        __syncthreads();

        float acc[2][4][4];
#pragma unroll
        for (int mf = 0; mf < 2; mf++)
#pragma unroll
            for (int nf = 0; nf < 4; nf++)
#pragma unroll
                for (int qq = 0; qq < 4; qq++) acc[mf][nf][qq] = 0.f;

#pragma unroll
        for (int c = 0; c < 8; c++) {
            uint32_t a[2][4], bfr[8];
            ldB(bfr, Bt, wn, c, lane);
            LDM4(a[0], ldm_addrA(As, c, 0, lane));
            LDM4(a[1], ldm_addrA(As, c, 1, lane));
#pragma unroll
            for (int mf = 0; mf < 2; mf++)
#pragma unroll
                for (int nf = 0; nf < 4; nf++)
                    MMA(acc[mf][nf], a[mf], bfr[2 * nf], bfr[2 * nf + 1]);
        }
#pragma unroll
        for (int c = 0; c < 8; c++) {
            uint32_t a[2][4], bfr[8];
            ldB(bfr, Bb, wn, c, lane);
            LDM4(a[0], ldm_addrA(As + 8192, c, 0, lane));
            LDM4(a[1], ldm_addrA(As + 8192, c, 1, lane));
#pragma unroll
            for (int mf = 0; mf < 2; mf++)
#pragma unroll
                for (int nf = 0; nf < 4; nf++)
                    MMA(acc[mf][nf], a[mf], bfr[2 * nf], bfr[2 * nf + 1]);
        }
        __syncthreads();

#pragma unroll
        for (int mf = 0; mf < 2; mf++) {
#pragma unroll
            for (int rh = 0; rh < 2; rh++) {
                const int r = mf * 16 + rh * 8 + ro;
#pragma unroll
                for (int p = 0; p < 2; p++) {
                    float4 b = b1r[p];
                    float v0 = silu_f(acc[mf][2 * p][2 * rh] + b.x);
                    float v1 = silu_f(acc[mf][2 * p][2 * rh + 1] + b.y);
                    float v2 = silu_f(acc[mf][2 * p + 1][2 * rh] + b.z);
                    float v3 = silu_f(acc[mf][2 * p + 1][2 * rh + 1] + b.w);
                    uint2 hv = make_uint2(pk2f(v0, v1), pk2f(v2, v3));
                    *(uint2*)(sm + img_offA(wn * 2 + p, r, q >> 1) + (q & 1) * 8) = hv;
                }
            }
        }
        __syncthreads();

#pragma unroll
        for (int mf = 0; mf < 2; mf++)
#pragma unroll
            for (int nf = 0; nf < 4; nf++)
#pragma unroll
                for (int qq = 0; qq < 4; qq++) acc[mf][nf][qq] = 0.f;
#pragma unroll
        for (int c = 0; c < 8; c++) {
            uint32_t a[2][4], bfr[8];
            ldB(bfr, B2, wn, c, lane);
            LDM4(a[0], ldm_addrA(As, c, 0, lane));
            LDM4(a[1], ldm_addrA(As, c, 1, lane));
#pragma unroll
            for (int mf = 0; mf < 2; mf++)
#pragma unroll
                for (int nf = 0; nf < 4; nf++)
                    MMA(acc[mf][nf], a[mf], bfr[2 * nf], bfr[2 * nf + 1]);
        }
#pragma unroll
        for (int mf = 0; mf < 2; mf++) {
#pragma unroll
            for (int rh = 0; rh < 2; rh++) {
                const int r = mf * 16 + rh * 8 + ro;
                const long gr = rowbase + r;
#pragma unroll
                for (int p = 0; p < 2; p++) {
                    const int cc = wn * 32 + p * 16 + q * 4;
                    float4 t = __ldg((const float4*)(nodes + gr * DD + cc));
                    float4 b = b2r[p];
                    float4 o = make_float4(
                        acc[mf][2 * p][2 * rh] + t.x + b.x,
                        acc[mf][2 * p][2 * rh + 1] + t.y + b.y,
                        acc[mf][2 * p + 1][2 * rh] + t.z + b.z,
                        acc[mf][2 * p + 1][2 * rh + 1] + t.w + b.w);
                    __stcs((float4*)(Out + gr * DD + cc), o);   // streaming store
                }
            }
        }
        __syncthreads();
    }
}

// ---------------- launch ----------------
extern "C" void kernel_launch(void* const* d_in, const int* in_sizes, int n_in,
                              void* d_out, int out_size) {
    const float* nodes = (const float*)d_in[0];
    const int*   ei    = (const int*)d_in[1];
    const float* ef    = (const float*)d_in[2];
    const float* mw1   = (const float*)d_in[3];
    const float* mb1   = (const float*)d_in[4];
    const float* uw1   = (const float*)d_in[5];
    const float* ub1   = (const float*)d_in[6];
    const float* uw2   = (const float*)d_in[7];
    const float* ub2   = (const float*)d_in[8];
    float* out = (float*)d_out;

    unsigned* Bf;
    __half *Ph, *aggh;
    cudaGetSymbolAddress((void**)&Bf,   g_Bfrag);
    cudaGetSymbolAddress((void**)&Ph,   g_Ph);
    cudaGetSymbolAddress((void**)&aggh, g_aggh);

    cudaFuncSetAttribute(tgemm<false, true, true, true, true, false>,
                         cudaFuncAttributeMaxDynamicSharedMemorySize, SMEM_EDGE);

    // 0) B fragment images + zero agg
    prep_kernel<<<69, 256>>>(mw1, uw1, uw2);
    // 1) Ph = fp16(nodes @ mw1_top + mb1)
    tgemm<true, false, false, false, false, true><<<NGRID, NTHREADS, SMEM_GEMM>>>(
        nodes, Bf + 0 * 8192, nullptr, mb1, nullptr, nullptr, Ph, NNODES);
    // 2) aggh[dst] += fp16(silu(ef @ mw1_bot + Ph[src]))
    tgemm<false, true, true, true, true, false><<<NGRID, NTHREADS, SMEM_EDGE>>>(
        ef, Bf + 1 * 8192, Ph, nullptr, ei, ei + NEDGES, aggh, NEDGES);
    // 3) out = silu([nodes|aggh] @ uw1 + ub1) @ uw2 + nodes + ub2  (fused)
    fusedk<<<NGRID_F, NTHREADS, SMEM_FUSED>>>(
        nodes, aggh, Bf + 2 * 8192, Bf + 3 * 8192, Bf + 4 * 8192, ub1, ub2, out);
}